// round 2
// baseline (speedup 1.0000x reference)
#include <cuda_runtime.h>
#include <cuda_bf16.h>

#define N_NODES 100000
#define DIM     128
#define N_ANCH  4096
#define N_SAMP  512
#define INV_TEMP 10.0f

// Scratch: inverse L2 norms of each row of x. 400 KB device global (allowed).
__device__ float g_invnorm[N_NODES];

// Kernel 1: warp per row -> inverse norm. Also zeroes the output scalar.
__global__ void invnorm_kernel(const float* __restrict__ x, float* __restrict__ out) {
    if (blockIdx.x == 0 && threadIdx.x == 0) out[0] = 0.0f;

    int warps_per_block = blockDim.x >> 5;
    int row = blockIdx.x * warps_per_block + (threadIdx.x >> 5);
    if (row >= N_NODES) return;
    int lane = threadIdx.x & 31;

    // 128 floats / row = one float4 per lane (coalesced 512B)
    const float4* xr = reinterpret_cast<const float4*>(x + (size_t)row * DIM);
    float4 v = xr[lane];
    float s = v.x * v.x + v.y * v.y + v.z * v.z + v.w * v.w;
    #pragma unroll
    for (int o = 16; o; o >>= 1) s += __shfl_xor_sync(0xffffffffu, s, o);
    if (lane == 0) g_invnorm[row] = rsqrtf(s);
}

// Kernel 2: one block per anchor, 8 warps, warp-per-sample.
__global__ __launch_bounds__(256) void supcon_kernel(
    const float* __restrict__ x,
    const int*   __restrict__ y,
    const int*   __restrict__ anchors,
    const int*   __restrict__ sampled,
    float*       __restrict__ out)
{
    const int a    = blockIdx.x;
    const int lane = threadIdx.x & 31;
    const int warp = threadIdx.x >> 5;

    __shared__ float af[DIM];
    __shared__ float s_num[8], s_den[8], s_cnt[8];
    __shared__ float s_inva;
    __shared__ int   s_ya;

    const int anchor = anchors[a];
    if (threadIdx.x < 32) {
        // warp 0 loads the anchor feature row (coalesced)
        float4 v = reinterpret_cast<const float4*>(x + (size_t)anchor * DIM)[lane];
        reinterpret_cast<float4*>(af)[lane] = v;
        if (lane == 0) {
            s_inva = g_invnorm[anchor];
            s_ya   = y[anchor];
        }
    }
    __syncthreads();

    const float4 av   = reinterpret_cast<const float4*>(af)[lane];
    const float  inva = s_inva;
    const int    ya   = s_ya;

    float num = 0.0f, den = 0.0f, cnt = 0.0f;

    const int* samp = sampled + (size_t)a * N_SAMP;

    // 64 samples per warp; each sample = one coalesced 512B row load.
    for (int si = warp; si < N_SAMP; si += 8) {
        const int idx = samp[si];  // uniform within warp -> broadcast load
        float4 sv = reinterpret_cast<const float4*>(x + (size_t)idx * DIM)[lane];
        float d = av.x * sv.x + av.y * sv.y + av.z * sv.z + av.w * sv.w;
        #pragma unroll
        for (int o = 16; o; o >>= 1) d += __shfl_xor_sync(0xffffffffu, d, o);
        // All lanes now hold the full dot; uniform broadcast loads below.
        const float sim = d * inva * g_invnorm[idx];
        const float e   = __expf(sim * INV_TEMP);
        den += e;
        if (y[idx] == ya) { num += e; cnt += 1.0f; }
    }

    // All lanes in a warp accumulated identical sums; lane 0's copy is canonical.
    if (lane == 0) { s_num[warp] = num; s_den[warp] = den; s_cnt[warp] = cnt; }
    __syncthreads();

    if (threadIdx.x == 0) {
        float tn = 0.0f, td = 0.0f, tc = 0.0f;
        #pragma unroll
        for (int w = 0; w < 8; w++) { tn += s_num[w]; td += s_den[w]; tc += s_cnt[w]; }
        float loss = 0.0f;
        if (tc > 0.0f) loss = -logf(tn / td) / tc;
        atomicAdd(out, loss);
    }
}

extern "C" void kernel_launch(void* const* d_in, const int* in_sizes, int n_in,
                              void* d_out, int out_size) {
    const float* x       = (const float*)d_in[0];
    const int*   y       = (const int*)  d_in[1];
    const int*   anchors = (const int*)  d_in[2];
    const int*   sampled = (const int*)  d_in[3];
    float*       out     = (float*)d_out;

    // invnorm: warp per row, 8 warps/block
    const int wpb = 8;
    const int blocks = (N_NODES + wpb - 1) / wpb;
    invnorm_kernel<<<blocks, wpb * 32>>>(x, out);

    supcon_kernel<<<N_ANCH, 256>>>(x, y, anchors, sampled, out);
}

// round 3
// speedup vs baseline: 1.3017x; 1.3017x over previous
#include <cuda_runtime.h>
#include <cuda_bf16.h>

#define N_NODES 100000
#define DIM     128
#define N_ANCH  4096
#define N_SAMP  512
#define INV_TEMP 10.0f

// Scratch: inverse L2 norms of each row of x. 400 KB device global (allowed).
__device__ float g_invnorm[N_NODES];

// Kernel 1: warp per row -> inverse norm. Also zeroes the output scalar.
__global__ void invnorm_kernel(const float* __restrict__ x, float* __restrict__ out) {
    if (blockIdx.x == 0 && threadIdx.x == 0) out[0] = 0.0f;

    int warps_per_block = blockDim.x >> 5;
    int row = blockIdx.x * warps_per_block + (threadIdx.x >> 5);
    if (row >= N_NODES) return;
    int lane = threadIdx.x & 31;

    const float4* xr = reinterpret_cast<const float4*>(x + (size_t)row * DIM);
    float4 v = xr[lane];
    float s = v.x * v.x + v.y * v.y + v.z * v.z + v.w * v.w;
    #pragma unroll
    for (int o = 16; o; o >>= 1) s += __shfl_xor_sync(0xffffffffu, s, o);
    if (lane == 0) g_invnorm[row] = rsqrtf(s);
}

// Kernel 2: one block per anchor, 8 warps.
// Each warp processes 8 samples per iteration with independent load/dot/shuffle
// chains so latency overlaps (8 samples in flight per warp).
__global__ __launch_bounds__(256) void supcon_kernel(
    const float* __restrict__ x,
    const int*   __restrict__ y,
    const int*   __restrict__ anchors,
    const int*   __restrict__ sampled,
    float*       __restrict__ out)
{
    const int a    = blockIdx.x;
    const int lane = threadIdx.x & 31;
    const int warp = threadIdx.x >> 5;

    __shared__ float af[DIM];
    __shared__ float s_num[8], s_den[8], s_cnt[8];
    __shared__ float s_inva;
    __shared__ int   s_ya;

    const int anchor = anchors[a];
    if (threadIdx.x < 32) {
        float4 v = reinterpret_cast<const float4*>(x + (size_t)anchor * DIM)[lane];
        reinterpret_cast<float4*>(af)[lane] = v;
        if (lane == 0) {
            s_inva = g_invnorm[anchor];
            s_ya   = y[anchor];
        }
    }
    __syncthreads();

    const float4 av   = reinterpret_cast<const float4*>(af)[lane];
    const float  inva = s_inva;
    const int    ya   = s_ya;

    float num = 0.0f, den = 0.0f, cnt = 0.0f;

    // Sample indices for this anchor, read 8 at a time (two int4, warp-uniform).
    const int4* samp4 = reinterpret_cast<const int4*>(sampled + (size_t)a * N_SAMP);

    // 512 samples / (8 warps * 8 samples) = 8 iterations.
    #pragma unroll 2
    for (int it = 0; it < 8; ++it) {
        const int b = it * 16 + warp * 2;          // int4 units
        const int4 i0 = samp4[b];
        const int4 i1 = samp4[b + 1];
        int idx[8];
        idx[0] = i0.x; idx[1] = i0.y; idx[2] = i0.z; idx[3] = i0.w;
        idx[4] = i1.x; idx[5] = i1.y; idx[6] = i1.z; idx[7] = i1.w;

        // Prefetch broadcast scalars early (overlaps with row loads).
        float inv_s[8];
        int   ys[8];
        #pragma unroll
        for (int j = 0; j < 8; ++j) {
            inv_s[j] = g_invnorm[idx[j]];
            ys[j]    = y[idx[j]];
        }

        // 8 independent coalesced 512B row loads + dot partials.
        float d[8];
        #pragma unroll
        for (int j = 0; j < 8; ++j) {
            float4 sv = reinterpret_cast<const float4*>(x + (size_t)idx[j] * DIM)[lane];
            d[j] = av.x * sv.x + av.y * sv.y + av.z * sv.z + av.w * sv.w;
        }

        // 8 interleaved butterflies: stages pipeline across samples.
        #pragma unroll
        for (int o = 16; o; o >>= 1) {
            #pragma unroll
            for (int j = 0; j < 8; ++j)
                d[j] += __shfl_xor_sync(0xffffffffu, d[j], o);
        }

        #pragma unroll
        for (int j = 0; j < 8; ++j) {
            const float sim = d[j] * inva * inv_s[j];
            const float e   = __expf(sim * INV_TEMP);
            const float m   = (ys[j] == ya) ? 1.0f : 0.0f;
            den += e;
            num += m * e;
            cnt += m;
        }
    }

    // All lanes hold identical warp totals; lane 0 is canonical.
    if (lane == 0) { s_num[warp] = num; s_den[warp] = den; s_cnt[warp] = cnt; }
    __syncthreads();

    if (threadIdx.x == 0) {
        float tn = 0.0f, td = 0.0f, tc = 0.0f;
        #pragma unroll
        for (int w = 0; w < 8; w++) { tn += s_num[w]; td += s_den[w]; tc += s_cnt[w]; }
        float loss = 0.0f;
        if (tc > 0.0f) loss = -logf(tn / td) / tc;
        atomicAdd(out, loss);
    }
}

extern "C" void kernel_launch(void* const* d_in, const int* in_sizes, int n_in,
                              void* d_out, int out_size) {
    const float* x       = (const float*)d_in[0];
    const int*   y       = (const int*)  d_in[1];
    const int*   anchors = (const int*)  d_in[2];
    const int*   sampled = (const int*)  d_in[3];
    float*       out     = (float*)d_out;

    const int wpb = 8;
    const int blocks = (N_NODES + wpb - 1) / wpb;
    invnorm_kernel<<<blocks, wpb * 32>>>(x, out);

    supcon_kernel<<<N_ANCH, 256>>>(x, y, anchors, sampled, out);
}

// round 4
// speedup vs baseline: 2.3411x; 1.7984x over previous
#include <cuda_runtime.h>
#include <cuda_fp16.h>

#define N_NODES 100000
#define DIM     128
#define N_ANCH  4096
#define N_SAMP  512
#define INV_TEMP 10.0f

// Normalized feature table in fp16: 100000 * 128 * 2B = 25.6 MB (fits L2).
__device__ __half g_xn[(size_t)N_NODES * DIM];

// Kernel 1: warp per row -> L2-normalize, store fp16. Also zero the output.
__global__ void normalize_kernel(const float* __restrict__ x, float* __restrict__ out) {
    if (blockIdx.x == 0 && threadIdx.x == 0) out[0] = 0.0f;

    int row = blockIdx.x * (blockDim.x >> 5) + (threadIdx.x >> 5);
    if (row >= N_NODES) return;
    int lane = threadIdx.x & 31;

    float4 v = reinterpret_cast<const float4*>(x + (size_t)row * DIM)[lane];
    float s = v.x * v.x + v.y * v.y + v.z * v.z + v.w * v.w;
    #pragma unroll
    for (int o = 16; o; o >>= 1) s += __shfl_xor_sync(0xffffffffu, s, o);
    float inv = rsqrtf(s);

    __half2 h0 = __floats2half2_rn(v.x * inv, v.y * inv);
    __half2 h1 = __floats2half2_rn(v.z * inv, v.w * inv);
    uint2 u;
    u.x = *reinterpret_cast<unsigned*>(&h0);
    u.y = *reinterpret_cast<unsigned*>(&h1);
    reinterpret_cast<uint2*>(g_xn + (size_t)row * DIM)[lane] = u;
}

// Kernel 2: one block per anchor, 8 warps, 8 samples per warp-batch.
// Packed multi-value warp reduce: 9 shuffles reduce 8 dots; lane ends up
// holding the full dot of sample sigma(lane) = 4*b2 + 2*b3 + b4.
__global__ __launch_bounds__(256) void supcon_kernel(
    const int*   __restrict__ y,
    const int*   __restrict__ anchors,
    const int*   __restrict__ sampled,
    float*       __restrict__ out)
{
    const int a    = blockIdx.x;
    const int lane = threadIdx.x & 31;
    const int warp = threadIdx.x >> 5;
    const int sig  = (((lane >> 2) & 1) << 2) | (((lane >> 3) & 1) << 1) | ((lane >> 4) & 1);

    __shared__ float s_num[8], s_den[8], s_cnt[8];

    const int anchor = anchors[a];
    const int ya     = y[anchor];

    // Anchor row (fp16 normalized), 4 dims per lane.
    float4 av;
    {
        uint2 u = reinterpret_cast<const uint2*>(g_xn + (size_t)anchor * DIM)[lane];
        __half2 h0 = *reinterpret_cast<__half2*>(&u.x);
        __half2 h1 = *reinterpret_cast<__half2*>(&u.y);
        float2 f0 = __half22float2(h0), f1 = __half22float2(h1);
        av = make_float4(f0.x, f0.y, f1.x, f1.y);
    }

    float num = 0.0f, den = 0.0f, cnt = 0.0f;

    const int*  samp  = sampled + (size_t)a * N_SAMP;
    const int4* samp4 = reinterpret_cast<const int4*>(samp);

    #pragma unroll 2
    for (int it = 0; it < 8; ++it) {
        const int base8 = it * 64 + warp * 8;       // first sample of this warp's batch

        // Warp-uniform indices for the 8 row gathers.
        const int4 i0 = samp4[(base8 >> 2)];
        const int4 i1 = samp4[(base8 >> 2) + 1];
        int idx[8] = { i0.x, i0.y, i0.z, i0.w, i1.x, i1.y, i1.z, i1.w };

        // Per-lane: which sample this lane will own after the packed reduce.
        const int my_idx = samp[base8 + sig];
        const int my_y   = y[my_idx];

        // 8 independent 256B fp16 row loads + partial dots (4 dims/lane).
        float d[8];
        #pragma unroll
        for (int j = 0; j < 8; ++j) {
            uint2 u = reinterpret_cast<const uint2*>(g_xn + (size_t)idx[j] * DIM)[lane];
            __half2 h0 = *reinterpret_cast<__half2*>(&u.x);
            __half2 h1 = *reinterpret_cast<__half2*>(&u.y);
            float2 f0 = __half22float2(h0), f1 = __half22float2(h1);
            d[j] = av.x * f0.x + av.y * f0.y + av.z * f1.x + av.w * f1.y;
        }

        // Packed reduce: fold bit4 (select by bit4), bit3, bit2, then 2,1.
        float e4[4];
        #pragma unroll
        for (int j = 0; j < 4; ++j) {
            float t = (lane & 16) ? d[2*j] : d[2*j + 1];
            float r = __shfl_xor_sync(0xffffffffu, t, 16);
            e4[j] = ((lane & 16) ? d[2*j + 1] : d[2*j]) + r;
        }
        float f2[2];
        #pragma unroll
        for (int j = 0; j < 2; ++j) {
            float t = (lane & 8) ? e4[2*j] : e4[2*j + 1];
            float r = __shfl_xor_sync(0xffffffffu, t, 8);
            f2[j] = ((lane & 8) ? e4[2*j + 1] : e4[2*j]) + r;
        }
        float t = (lane & 4) ? f2[0] : f2[1];
        float r = __shfl_xor_sync(0xffffffffu, t, 4);
        float g = ((lane & 4) ? f2[1] : f2[0]) + r;
        g += __shfl_xor_sync(0xffffffffu, g, 2);
        g += __shfl_xor_sync(0xffffffffu, g, 1);
        // g = full dot of sample (base8 + sig); each sample held by 4 lanes.

        const float e = __expf(g * INV_TEMP);
        const float m = (my_y == ya) ? 1.0f : 0.0f;
        den += e;
        num += m * e;
        cnt += m;
    }

    // Each sample was accumulated by 4 lanes -> scale by 0.25 after reduce.
    #pragma unroll
    for (int o = 16; o; o >>= 1) {
        den += __shfl_xor_sync(0xffffffffu, den, o);
        num += __shfl_xor_sync(0xffffffffu, num, o);
        cnt += __shfl_xor_sync(0xffffffffu, cnt, o);
    }
    if (lane == 0) {
        s_num[warp] = num * 0.25f;
        s_den[warp] = den * 0.25f;
        s_cnt[warp] = cnt * 0.25f;
    }
    __syncthreads();

    if (threadIdx.x == 0) {
        float tn = 0.0f, td = 0.0f, tc = 0.0f;
        #pragma unroll
        for (int w = 0; w < 8; w++) { tn += s_num[w]; td += s_den[w]; tc += s_cnt[w]; }
        float loss = 0.0f;
        if (tc > 0.0f) loss = -logf(tn / td) / tc;
        atomicAdd(out, loss);
    }
}

extern "C" void kernel_launch(void* const* d_in, const int* in_sizes, int n_in,
                              void* d_out, int out_size) {
    const float* x       = (const float*)d_in[0];
    const int*   y       = (const int*)  d_in[1];
    const int*   anchors = (const int*)  d_in[2];
    const int*   sampled = (const int*)  d_in[3];
    float*       out     = (float*)d_out;

    const int wpb = 8;
    const int blocks = (N_NODES + wpb - 1) / wpb;
    normalize_kernel<<<blocks, wpb * 32>>>(x, out);

    supcon_kernel<<<N_ANCH, 256>>>(y, anchors, sampled, out);
}